// round 1
// baseline (speedup 1.0000x reference)
#include <cuda_runtime.h>
#include <cuda_bf16.h>

// Problem constants (fixed by the reference): imgs [8,3,1024,1024] fp32, z [N,2] fp32, out [8,2] fp32
#define NY  1024
#define NX  1024
#define NBC 24              // B*C = 8*3 channel-planes
#define GATHER_BLOCKS 888   // 148 SMs * 6 resident blocks

// Scratch: transposed images T[y][x][bc] (96 MiB) + per-block partials.
// __device__ globals are the sanctioned scratch mechanism (no cudaMalloc allowed).
__device__ __align__(128) float g_T[(size_t)NY * NX * NBC];
__device__ float g_partial[GATHER_BLOCKS * 16];

// ---------------------------------------------------------------------------
// Kernel 1: transpose imgs[bc][y][x] -> g_T[y][x][bc]
// Block = 128 threads, handles one y-row and a 128-wide x tile.
// Reads: 24 coalesced 512B row segments. Writes: one contiguous 12KB region
// (128 pixels * 24 ch) via float4 — DRAM-bound both ways (~192MB total).
// ---------------------------------------------------------------------------
__global__ void __launch_bounds__(128) transpose_kernel(const float* __restrict__ imgs) {
    __shared__ float sm[128 * 25];         // pad 24->25 for conflict-free STS
    const int y   = blockIdx.x >> 3;
    const int x0  = (blockIdx.x & 7) << 7; // tile * 128
    const int tid = threadIdx.x;

    #pragma unroll
    for (int bc = 0; bc < NBC; bc++) {
        sm[tid * 25 + bc] = imgs[((size_t)bc * NY + y) * NX + x0 + tid];
    }
    __syncthreads();

    // 128*24 = 3072 floats = 768 float4, contiguous in g_T (16B aligned: 96B granules)
    float4* out4 = reinterpret_cast<float4*>(g_T + ((size_t)y * NX + x0) * NBC);
    #pragma unroll
    for (int k = 0; k < 6; k++) {
        int m4 = k * 128 + tid;
        int m  = m4 * 4;
        float4 v;
        v.x = sm[((m    ) / 24) * 25 + ((m    ) % 24)];
        v.y = sm[((m + 1) / 24) * 25 + ((m + 1) % 24)];
        v.z = sm[((m + 2) / 24) * 25 + ((m + 2) % 24)];
        v.w = sm[((m + 3) / 24) * 25 + ((m + 3) % 24)];
        out4[m4] = v;
    }
}

// ---------------------------------------------------------------------------
// Kernel 2: warp-per-point gather/accumulate.
// Lanes 0..23 own channel-plane bc=lane; the 4 taps per point are 24-lane
// coalesced 96B loads (exactly 3 sectors each, zero wasted bytes).
//   gc0 = (1+fx)(g10-g00) + fx(g01-g11)
//   gc1 = (1+fy)(g01-g00) + fy(g10-g11)
// Deterministic: fixed warp-strided point assignment, fixed-order block reduce.
// ---------------------------------------------------------------------------
__global__ void __launch_bounds__(256, 6) gather_kernel(const float* __restrict__ z, int n) {
    const int tid  = threadIdx.x;
    const int lane = tid & 31;
    const int wid  = tid >> 5;                   // warp in block (0..7)
    const int gw   = blockIdx.x * 8 + wid;       // global warp id
    const int W    = gridDim.x * 8;              // total warps

    float acc0 = 0.f, acc1 = 0.f;
    const float2* __restrict__ z2 = reinterpret_cast<const float2*>(z);

    for (int p = gw; p < n; p += W) {
        float2 zz = __ldg(&z2[p]);               // lane-uniform broadcast load
        float x0y = zz.x * 1023.0f;
        float x0x = zz.y * 1023.0f;
        bool oob = (x0y < 0.f) | (x0y > 1023.f) | (x0x < 0.f) | (x0x > 1023.f);
        if (oob) { x0y = 0.f; x0x = 0.f; }
        float ygf = floorf(x0y), xgf = floorf(x0x);
        int   yg = (int)ygf,    xg = (int)xgf;
        float fy = ygf - x0y,   fx = xgf - x0x;  // in (-1, 0]
        float valid = oob ? 0.f : 1.f;
        float w1x = (1.f + fx) * valid, wxv = fx * valid;
        float w1y = (1.f + fy) * valid, wyv = fy * valid;
        int yg1 = min(yg + 1, NY - 1);           // jax-style clamp (safety)
        int xg1 = min(xg + 1, NX - 1);

        if (lane < NBC) {
            int r0 = yg  * NX;
            int r1 = yg1 * NX;
            float g00 = __ldg(g_T + (size_t)(r0 + xg ) * NBC + lane);
            float g01 = __ldg(g_T + (size_t)(r0 + xg1) * NBC + lane);
            float g10 = __ldg(g_T + (size_t)(r1 + xg ) * NBC + lane);
            float g11 = __ldg(g_T + (size_t)(r1 + xg1) * NBC + lane);
            acc0 += w1x * (g10 - g00) + wxv * (g01 - g11);
            acc1 += w1y * (g01 - g00) + wyv * (g10 - g11);
        }
    }

    __shared__ float s[8][NBC][2];
    if (lane < NBC) { s[wid][lane][0] = acc0; s[wid][lane][1] = acc1; }
    __syncthreads();

    // Per-block partial: out[b][o], b = bc/3. Fixed-order sums -> deterministic.
    if (tid < 16) {
        int b = tid >> 1, o = tid & 1;
        float sum = 0.f;
        #pragma unroll
        for (int w = 0; w < 8; w++)
            #pragma unroll
            for (int cc = 0; cc < 3; cc++)
                sum += s[w][b * 3 + cc][o];
        g_partial[blockIdx.x * 16 + tid] = sum;
    }
}

// ---------------------------------------------------------------------------
// Kernel 3: deterministic final reduction of GATHER_BLOCKS x 16 partials.
// ---------------------------------------------------------------------------
__global__ void __launch_bounds__(256) reduce_kernel(float* __restrict__ out) {
    __shared__ float red[256];
    const int tid = threadIdx.x;
    const int j = tid & 15, g = tid >> 4;        // 16 outputs x 16 lanes each
    float sum = 0.f;
    for (int i = g; i < GATHER_BLOCKS; i += 16)
        sum += g_partial[i * 16 + j];
    red[tid] = sum;
    __syncthreads();
    if (tid < 16) {
        float s2 = 0.f;
        #pragma unroll
        for (int g2 = 0; g2 < 16; g2++)
            s2 += red[g2 * 16 + tid];
        out[tid] = s2;
    }
}

extern "C" void kernel_launch(void* const* d_in, const int* in_sizes, int n_in,
                              void* d_out, int out_size) {
    const float* imgs = (const float*)d_in[0];   // 8*3*1024*1024 fp32
    const float* z    = (const float*)d_in[1];   // N*2 fp32
    const int n_pts   = in_sizes[1] / 2;

    transpose_kernel<<<NY * (NX / 128), 128>>>(imgs);
    gather_kernel<<<GATHER_BLOCKS, 256>>>(z, n_pts);
    reduce_kernel<<<1, 256>>>((float*)d_out);
}

// round 2
// speedup vs baseline: 1.0011x; 1.0011x over previous
#include <cuda_runtime.h>
#include <cuda_bf16.h>

// Problem constants (fixed by the reference): imgs [8,3,1024,1024] fp32, z [N,2] fp32, out [8,2] fp32
#define NY  1024
#define NX  1024
#define NBC 24              // B*C = 8*3 channel-planes
#define GATHER_BLOCKS 888   // 148 SMs * 6 resident blocks

// Scratch: transposed images T[y][x][bc] (96 MiB) + per-block partials.
// __device__ globals are the sanctioned scratch mechanism (no cudaMalloc allowed).
__device__ __align__(128) float g_T[(size_t)NY * NX * NBC];
__device__ float g_partial[GATHER_BLOCKS * 16];

// ---------------------------------------------------------------------------
// Kernel 1: transpose imgs[bc][y][x] -> g_T[y][x][bc]
// Block = 128 threads, handles one y-row and a 128-wide x tile.
// Reads: 24 coalesced 512B row segments. Writes: one contiguous 12KB region
// (128 pixels * 24 ch) via float4 — DRAM-bound both ways (~192MB total).
// ---------------------------------------------------------------------------
__global__ void __launch_bounds__(128) transpose_kernel(const float* __restrict__ imgs) {
    __shared__ float sm[128 * 25];         // pad 24->25 for conflict-free STS
    const int y   = blockIdx.x >> 3;
    const int x0  = (blockIdx.x & 7) << 7; // tile * 128
    const int tid = threadIdx.x;

    #pragma unroll
    for (int bc = 0; bc < NBC; bc++) {
        sm[tid * 25 + bc] = imgs[((size_t)bc * NY + y) * NX + x0 + tid];
    }
    __syncthreads();

    // 128*24 = 3072 floats = 768 float4, contiguous in g_T (16B aligned: 96B granules)
    float4* out4 = reinterpret_cast<float4*>(g_T + ((size_t)y * NX + x0) * NBC);
    #pragma unroll
    for (int k = 0; k < 6; k++) {
        int m4 = k * 128 + tid;
        int m  = m4 * 4;
        float4 v;
        v.x = sm[((m    ) / 24) * 25 + ((m    ) % 24)];
        v.y = sm[((m + 1) / 24) * 25 + ((m + 1) % 24)];
        v.z = sm[((m + 2) / 24) * 25 + ((m + 2) % 24)];
        v.w = sm[((m + 3) / 24) * 25 + ((m + 3) % 24)];
        out4[m4] = v;
    }
}

// ---------------------------------------------------------------------------
// Kernel 2: warp-per-point gather/accumulate.
// Lanes 0..23 own channel-plane bc=lane; the 4 taps per point are 24-lane
// coalesced 96B loads (exactly 3 sectors each, zero wasted bytes).
//   gc0 = (1+fx)(g10-g00) + fx(g01-g11)
//   gc1 = (1+fy)(g01-g00) + fy(g10-g11)
// Deterministic: fixed warp-strided point assignment, fixed-order block reduce.
// ---------------------------------------------------------------------------
__global__ void __launch_bounds__(256, 6) gather_kernel(const float* __restrict__ z, int n) {
    const int tid  = threadIdx.x;
    const int lane = tid & 31;
    const int wid  = tid >> 5;                   // warp in block (0..7)
    const int gw   = blockIdx.x * 8 + wid;       // global warp id
    const int W    = gridDim.x * 8;              // total warps

    float acc0 = 0.f, acc1 = 0.f;
    const float2* __restrict__ z2 = reinterpret_cast<const float2*>(z);

    for (int p = gw; p < n; p += W) {
        float2 zz = __ldg(&z2[p]);               // lane-uniform broadcast load
        float x0y = zz.x * 1023.0f;
        float x0x = zz.y * 1023.0f;
        bool oob = (x0y < 0.f) | (x0y > 1023.f) | (x0x < 0.f) | (x0x > 1023.f);
        if (oob) { x0y = 0.f; x0x = 0.f; }
        float ygf = floorf(x0y), xgf = floorf(x0x);
        int   yg = (int)ygf,    xg = (int)xgf;
        float fy = ygf - x0y,   fx = xgf - x0x;  // in (-1, 0]
        float valid = oob ? 0.f : 1.f;
        float w1x = (1.f + fx) * valid, wxv = fx * valid;
        float w1y = (1.f + fy) * valid, wyv = fy * valid;
        int yg1 = min(yg + 1, NY - 1);           // jax-style clamp (safety)
        int xg1 = min(xg + 1, NX - 1);

        if (lane < NBC) {
            int r0 = yg  * NX;
            int r1 = yg1 * NX;
            float g00 = __ldg(g_T + (size_t)(r0 + xg ) * NBC + lane);
            float g01 = __ldg(g_T + (size_t)(r0 + xg1) * NBC + lane);
            float g10 = __ldg(g_T + (size_t)(r1 + xg ) * NBC + lane);
            float g11 = __ldg(g_T + (size_t)(r1 + xg1) * NBC + lane);
            acc0 += w1x * (g10 - g00) + wxv * (g01 - g11);
            acc1 += w1y * (g01 - g00) + wyv * (g10 - g11);
        }
    }

    __shared__ float s[8][NBC][2];
    if (lane < NBC) { s[wid][lane][0] = acc0; s[wid][lane][1] = acc1; }
    __syncthreads();

    // Per-block partial: out[b][o], b = bc/3. Fixed-order sums -> deterministic.
    if (tid < 16) {
        int b = tid >> 1, o = tid & 1;
        float sum = 0.f;
        #pragma unroll
        for (int w = 0; w < 8; w++)
            #pragma unroll
            for (int cc = 0; cc < 3; cc++)
                sum += s[w][b * 3 + cc][o];
        g_partial[blockIdx.x * 16 + tid] = sum;
    }
}

// ---------------------------------------------------------------------------
// Kernel 3: deterministic final reduction of GATHER_BLOCKS x 16 partials.
// ---------------------------------------------------------------------------
__global__ void __launch_bounds__(256) reduce_kernel(float* __restrict__ out) {
    __shared__ float red[256];
    const int tid = threadIdx.x;
    const int j = tid & 15, g = tid >> 4;        // 16 outputs x 16 lanes each
    float sum = 0.f;
    for (int i = g; i < GATHER_BLOCKS; i += 16)
        sum += g_partial[i * 16 + j];
    red[tid] = sum;
    __syncthreads();
    if (tid < 16) {
        float s2 = 0.f;
        #pragma unroll
        for (int g2 = 0; g2 < 16; g2++)
            s2 += red[g2 * 16 + tid];
        out[tid] = s2;
    }
}

extern "C" void kernel_launch(void* const* d_in, const int* in_sizes, int n_in,
                              void* d_out, int out_size) {
    const float* imgs = (const float*)d_in[0];   // 8*3*1024*1024 fp32
    const float* z    = (const float*)d_in[1];   // N*2 fp32
    const int n_pts   = in_sizes[1] / 2;

    transpose_kernel<<<NY * (NX / 128), 128>>>(imgs);
    gather_kernel<<<GATHER_BLOCKS, 256>>>(z, n_pts);
    reduce_kernel<<<1, 256>>>((float*)d_out);
}

// round 3
// speedup vs baseline: 1.4464x; 1.4448x over previous
#include <cuda_runtime.h>
#include <cuda_bf16.h>

// Problem constants (fixed by the reference): imgs [8,3,1024,1024] fp32, z [N,2] fp32, out [8,2] fp32
#define NY  1024
#define NX  1024
#define NBC 24               // B*C = 8*3 channel-planes
#define GBLOCK 384           // gather block: 16 points x 24 channels
#define GPTS   16            // points per block per step
#define GATHER_BLOCKS 592    // 148 SMs * 4 resident blocks

// Scratch: transposed images T[y][x][bc] (96 MiB) + per-block partials.
__device__ __align__(128) float g_T[(size_t)NY * NX * NBC];
__device__ float g_partial[GATHER_BLOCKS * 16];

// ---------------------------------------------------------------------------
// Kernel 1: transpose imgs[bc][y][x] -> g_T[y][x][bc]   (unchanged from R1:
// 33.7us, DRAM 57%; near floor, kept frozen while gather is optimized)
// ---------------------------------------------------------------------------
__global__ void __launch_bounds__(128) transpose_kernel(const float* __restrict__ imgs) {
    __shared__ float sm[128 * 25];         // pad 24->25 for conflict-free STS
    const int y   = blockIdx.x >> 3;
    const int x0  = (blockIdx.x & 7) << 7; // tile * 128
    const int tid = threadIdx.x;

    #pragma unroll
    for (int bc = 0; bc < NBC; bc++) {
        sm[tid * 25 + bc] = imgs[((size_t)bc * NY + y) * NX + x0 + tid];
    }
    __syncthreads();

    float4* out4 = reinterpret_cast<float4*>(g_T + ((size_t)y * NX + x0) * NBC);
    #pragma unroll
    for (int k = 0; k < 6; k++) {
        int m4 = k * 128 + tid;
        int m  = m4 * 4;
        float4 v;
        v.x = sm[((m    ) / 24) * 25 + ((m    ) % 24)];
        v.y = sm[((m + 1) / 24) * 25 + ((m + 1) % 24)];
        v.z = sm[((m + 2) / 24) * 25 + ((m + 2) % 24)];
        v.w = sm[((m + 3) / 24) * 25 + ((m + 3) % 24)];
        out4[m4] = v;
    }
}

// ---------------------------------------------------------------------------
// Per-point gather step: thread owns (point p, channel bc).
//   gc0 = (1+fx)(g10-g00) + fx(g01-g11)
//   gc1 = (1+fy)(g01-g00) + fy(g10-g11)
// ---------------------------------------------------------------------------
__device__ __forceinline__ void proc_point(
    const float2* __restrict__ z2, const float* __restrict__ T,
    int p, int bc, float& acc0, float& acc1)
{
    float2 zz = __ldg(&z2[p]);
    float x0y = zz.x * 1023.0f;
    float x0x = zz.y * 1023.0f;
    bool oob = (x0y < 0.f) | (x0y > 1023.f) | (x0x < 0.f) | (x0x > 1023.f);
    if (oob) { x0y = 0.f; x0x = 0.f; }
    float ygf = floorf(x0y), xgf = floorf(x0x);
    int   yg = min((int)ygf, NY - 2);   // memory-safety clamp (z in [0,1) => never binds)
    int   xg = min((int)xgf, NX - 2);
    float fy = ygf - x0y,  fx = xgf - x0x;     // in (-1, 0]
    float valid = oob ? 0.f : 1.f;
    float w1x = (1.f + fx) * valid, wxv = fx * valid;
    float w1y = (1.f + fy) * valid, wyv = fy * valid;

    int i00 = (yg * NX + xg) * NBC + bc;
    float g00 = __ldg(T + i00);
    float g01 = __ldg(T + i00 + NBC);
    float g10 = __ldg(T + i00 + NBC * NX);
    float g11 = __ldg(T + i00 + NBC * NX + NBC);

    acc0 = fmaf(w1x, g10 - g00, fmaf(wxv, g01 - g11, acc0));
    acc1 = fmaf(w1y, g01 - g00, fmaf(wyv, g10 - g11, acc1));
}

// ---------------------------------------------------------------------------
// Kernel 2: full-lane gather. 384 threads = 16 points x 24 channels; every
// lane of every warp is productive. Unroll x2 -> 8 independent loads in
// flight per thread-pair of points. Deterministic fixed-order reduction.
// ---------------------------------------------------------------------------
__global__ void __launch_bounds__(GBLOCK, 4) gather_kernel(const float* __restrict__ z, int n) {
    const int t    = threadIdx.x;
    const int bc   = t % NBC;
    const int pl   = t / NBC;                       // 0..15
    const int base = blockIdx.x * GPTS + pl;
    const int S    = gridDim.x * GPTS;              // point stride per step

    const float2* __restrict__ z2 = reinterpret_cast<const float2*>(z);
    const float*  __restrict__ T  = g_T;

    float acc0 = 0.f, acc1 = 0.f;
    int p = base;
    for (; p + S < n; p += 2 * S) {
        proc_point(z2, T, p,     bc, acc0, acc1);
        proc_point(z2, T, p + S, bc, acc0, acc1);
    }
    for (; p < n; p += S)
        proc_point(z2, T, p, bc, acc0, acc1);

    __shared__ float s0[GBLOCK], s1[GBLOCK];
    s0[t] = acc0; s1[t] = acc1;
    __syncthreads();

    // Per-block partial: out[b][o], b = bc/3. Fixed-order sums -> deterministic.
    if (t < 16) {
        int b = t >> 1, o = t & 1;
        float sum = 0.f;
        #pragma unroll
        for (int q = 0; q < GPTS; q++)
            #pragma unroll
            for (int cc = 0; cc < 3; cc++) {
                int idx = q * NBC + b * 3 + cc;
                sum += o ? s1[idx] : s0[idx];
            }
        g_partial[blockIdx.x * 16 + t] = sum;
    }
}

// ---------------------------------------------------------------------------
// Kernel 3: deterministic final reduction of GATHER_BLOCKS x 16 partials.
// ---------------------------------------------------------------------------
__global__ void __launch_bounds__(256) reduce_kernel(float* __restrict__ out) {
    __shared__ float red[256];
    const int tid = threadIdx.x;
    const int j = tid & 15, g = tid >> 4;        // 16 outputs x 16 lanes each
    float sum = 0.f;
    for (int i = g; i < GATHER_BLOCKS; i += 16)
        sum += g_partial[i * 16 + j];
    red[tid] = sum;
    __syncthreads();
    if (tid < 16) {
        float s2 = 0.f;
        #pragma unroll
        for (int g2 = 0; g2 < 16; g2++)
            s2 += red[g2 * 16 + tid];
        out[tid] = s2;
    }
}

extern "C" void kernel_launch(void* const* d_in, const int* in_sizes, int n_in,
                              void* d_out, int out_size) {
    const float* imgs = (const float*)d_in[0];   // 8*3*1024*1024 fp32
    const float* z    = (const float*)d_in[1];   // N*2 fp32
    const int n_pts   = in_sizes[1] / 2;

    transpose_kernel<<<NY * (NX / 128), 128>>>(imgs);
    gather_kernel<<<GATHER_BLOCKS, GBLOCK>>>(z, n_pts);
    reduce_kernel<<<1, 256>>>((float*)d_out);
}

// round 4
// speedup vs baseline: 2.9470x; 2.0375x over previous
#include <cuda_runtime.h>
#include <cuda_bf16.h>

// Problem constants: imgs [8,3,1024,1024] fp32, z [N,2] fp32, out [8,2] fp32
#define NY  1024
#define NX  1024
#define NB  8                // batches (channel-folded)
#define GBLOCK 256           // gather block: 32 points x 8 batches
#define GPTS   32            // points per block per step
#define GATHER_BLOCKS 888    // 148 SMs * 6 resident blocks

// Scratch: channel-folded, pixel-major images P[y][x][b] (32 MiB, L2-resident)
__device__ __align__(128) float g_P[(size_t)NY * NX * NB];
__device__ float g_partial[GATHER_BLOCKS * 16];

// ---------------------------------------------------------------------------
// Kernel 1: fold+transpose  imgs[b*3+c][y][x] --sum_c--> g_P[y][x][b]
// Block = 128 threads, one y-row, 128-wide x tile.
// Reads 24 coalesced 512B segments (96MB total), writes one contiguous 4KB
// region (32MB total) via float4. Channel sum commutes with interpolation.
// ---------------------------------------------------------------------------
__global__ void __launch_bounds__(128) fold_kernel(const float* __restrict__ imgs) {
    __shared__ float sm[128 * 9];          // pad 8->9 for conflict-free access
    const int y   = blockIdx.x >> 3;
    const int x0  = (blockIdx.x & 7) << 7;
    const int tid = threadIdx.x;

    #pragma unroll
    for (int b = 0; b < NB; b++) {
        float s = 0.f;
        #pragma unroll
        for (int c = 0; c < 3; c++)
            s += imgs[((size_t)(b * 3 + c) * NY + y) * NX + x0 + tid];
        sm[tid * 9 + b] = s;
    }
    __syncthreads();

    // 128 pixels * 8 floats = 256 float4, contiguous (32B-aligned groups)
    float4* out4 = reinterpret_cast<float4*>(g_P + ((size_t)y * NX + x0) * NB);
    #pragma unroll
    for (int k = 0; k < 2; k++) {
        int j   = k * 128 + tid;
        int pix = j >> 1, h = (j & 1) * 4;
        float4 v;
        v.x = sm[pix * 9 + h    ];
        v.y = sm[pix * 9 + h + 1];
        v.z = sm[pix * 9 + h + 2];
        v.w = sm[pix * 9 + h + 3];
        out4[j] = v;
    }
}

// ---------------------------------------------------------------------------
// Per-point gather step: thread owns (point p, batch b). Each tap is one
// aligned 32B sector shared by the 8 lanes of this point.
//   gc0 = (1+fx)(g10-g00) + fx(g01-g11)
//   gc1 = (1+fy)(g01-g00) + fy(g10-g11)
// ---------------------------------------------------------------------------
__device__ __forceinline__ void proc_point(
    const float2* __restrict__ z2, const float* __restrict__ P,
    int p, int b, float& acc0, float& acc1)
{
    float2 zz = __ldg(&z2[p]);
    float x0y = zz.x * 1023.0f;
    float x0x = zz.y * 1023.0f;
    bool oob = (x0y < 0.f) | (x0y > 1023.f) | (x0x < 0.f) | (x0x > 1023.f);
    if (oob) { x0y = 0.f; x0x = 0.f; }
    float ygf = floorf(x0y), xgf = floorf(x0x);
    int   yg = min((int)ygf, NY - 2);   // memory-safety clamp (never binds for z in [0,1))
    int   xg = min((int)xgf, NX - 2);
    float fy = ygf - x0y,  fx = xgf - x0x;     // in (-1, 0]
    float valid = oob ? 0.f : 1.f;
    float w1x = (1.f + fx) * valid, wxv = fx * valid;
    float w1y = (1.f + fy) * valid, wyv = fy * valid;

    int i00 = (yg * NX + xg) * NB + b;
    float g00 = __ldg(P + i00);
    float g01 = __ldg(P + i00 + NB);
    float g10 = __ldg(P + i00 + NB * NX);
    float g11 = __ldg(P + i00 + NB * NX + NB);

    acc0 = fmaf(w1x, g10 - g00, fmaf(wxv, g01 - g11, acc0));
    acc1 = fmaf(w1y, g01 - g00, fmaf(wyv, g10 - g11, acc1));
}

// ---------------------------------------------------------------------------
// Kernel 2: full-lane gather over folded P. 256 threads = 32 points x 8
// batches; warp = 4 points, all lanes productive, 32B/tap perfectly aligned.
// Unroll x2 -> 8 independent loads in flight per thread. Deterministic.
// ---------------------------------------------------------------------------
__global__ void __launch_bounds__(GBLOCK, 6) gather_kernel(const float* __restrict__ z, int n) {
    const int t    = threadIdx.x;
    const int b    = t & 7;
    const int pl   = t >> 3;                        // 0..31
    const int base = blockIdx.x * GPTS + pl;
    const int S    = gridDim.x * GPTS;              // point stride per step

    const float2* __restrict__ z2 = reinterpret_cast<const float2*>(z);
    const float*  __restrict__ P  = g_P;

    float acc0 = 0.f, acc1 = 0.f;
    int p = base;
    for (; p + S < n; p += 2 * S) {
        proc_point(z2, P, p,     b, acc0, acc1);
        proc_point(z2, P, p + S, b, acc0, acc1);
    }
    for (; p < n; p += S)
        proc_point(z2, P, p, b, acc0, acc1);

    __shared__ float s0[GBLOCK], s1[GBLOCK];
    s0[t] = acc0; s1[t] = acc1;
    __syncthreads();

    // Per-block partial: out[b][o]. Fixed-order sums -> deterministic.
    if (t < 16) {
        int bb = t >> 1, o = t & 1;
        float sum = 0.f;
        #pragma unroll
        for (int q = 0; q < GPTS; q++) {
            int idx = q * NB + bb;
            sum += o ? s1[idx] : s0[idx];
        }
        g_partial[blockIdx.x * 16 + t] = sum;
    }
}

// ---------------------------------------------------------------------------
// Kernel 3: deterministic final reduction of GATHER_BLOCKS x 16 partials.
// ---------------------------------------------------------------------------
__global__ void __launch_bounds__(256) reduce_kernel(float* __restrict__ out) {
    __shared__ float red[256];
    const int tid = threadIdx.x;
    const int j = tid & 15, g = tid >> 4;        // 16 outputs x 16 lanes each
    float sum = 0.f;
    for (int i = g; i < GATHER_BLOCKS; i += 16)
        sum += g_partial[i * 16 + j];
    red[tid] = sum;
    __syncthreads();
    if (tid < 16) {
        float s2 = 0.f;
        #pragma unroll
        for (int g2 = 0; g2 < 16; g2++)
            s2 += red[g2 * 16 + tid];
        out[tid] = s2;
    }
}

extern "C" void kernel_launch(void* const* d_in, const int* in_sizes, int n_in,
                              void* d_out, int out_size) {
    const float* imgs = (const float*)d_in[0];   // 8*3*1024*1024 fp32
    const float* z    = (const float*)d_in[1];   // N*2 fp32
    const int n_pts   = in_sizes[1] / 2;

    fold_kernel<<<NY * (NX / 128), 128>>>(imgs);
    gather_kernel<<<GATHER_BLOCKS, GBLOCK>>>(z, n_pts);
    reduce_kernel<<<1, 256>>>((float*)d_out);
}